// round 1
// baseline (speedup 1.0000x reference)
#include <cuda_runtime.h>

// Problem shape (fixed by the dataset)
#define BATCH 32
#define NSEQ  512
#define DDIM  512

// Tile config
#define BM 64
#define BN 64
#define BK 16
#define TM 4
#define TN 4

// Scratch for Y = X @ W  (32 MB, device global — no allocation allowed)
__device__ float g_Y[BATCH * NSEQ * DDIM];

// ---------------------------------------------------------------------------
// GEMM1 (NN): C[M,N] = A[M,K] * B[K,N], all row-major.
// A = X flattened (16384 x 512), B = W (512 x 512), C = g_Y.
// ---------------------------------------------------------------------------
__global__ __launch_bounds__(256) void gemm_xw(
    const float* __restrict__ A, const float* __restrict__ B,
    float* __restrict__ C, int M, int N, int K)
{
    __shared__ float As[BK][BM + 4];   // transposed store, padded (bank conflicts)
    __shared__ float Bs[BK][BN];

    const int tid = threadIdx.x;
    const int bx = blockIdx.x;   // N tile
    const int by = blockIdx.y;   // M tile

    const float* Aptr = A + (size_t)by * BM * K;
    const float* Bptr = B + bx * BN;

    // A tile loaders: 64 rows x 16 cols, one float4 per thread
    const int arow = tid >> 2;
    const int acol = (tid & 3) * 4;
    // B tile loaders: 16 rows x 64 cols
    const int brow = tid >> 4;
    const int bcol = (tid & 15) * 4;
    // compute mapping
    const int ty = tid >> 4;     // 0..15 -> 4 rows each
    const int tx = tid & 15;     // 0..15 -> 4 cols each

    float acc[TM][TN] = {};

    for (int k0 = 0; k0 < K; k0 += BK) {
        float4 av = *(const float4*)(Aptr + (size_t)arow * K + k0 + acol);
        As[acol + 0][arow] = av.x;
        As[acol + 1][arow] = av.y;
        As[acol + 2][arow] = av.z;
        As[acol + 3][arow] = av.w;
        float4 bv = *(const float4*)(Bptr + (size_t)(k0 + brow) * N + bcol);
        *(float4*)&Bs[brow][bcol] = bv;
        __syncthreads();

#pragma unroll
        for (int k = 0; k < BK; k++) {
            float a[TM], bb[TN];
#pragma unroll
            for (int i = 0; i < TM; i++) a[i] = As[k][ty * TM + i];
#pragma unroll
            for (int j = 0; j < TN; j++) bb[j] = Bs[k][tx * TN + j];
#pragma unroll
            for (int i = 0; i < TM; i++)
#pragma unroll
                for (int j = 0; j < TN; j++)
                    acc[i][j] += a[i] * bb[j];
        }
        __syncthreads();
    }

    float* Cptr = C + (size_t)(by * BM) * N + bx * BN;
#pragma unroll
    for (int i = 0; i < TM; i++) {
        float4 v = make_float4(acc[i][0], acc[i][1], acc[i][2], acc[i][3]);
        *(float4*)(Cptr + (size_t)(ty * TM + i) * N + tx * TN) = v;
    }
}

// ---------------------------------------------------------------------------
// GEMM2 (NT, batched): S[b][i][j] = sum_k Y[b][i][k] * X[b][j][k] + bias
// diagonal (i==j) forced to 0.
// ---------------------------------------------------------------------------
__global__ __launch_bounds__(256) void gemm_yxt(
    const float* __restrict__ Y, const float* __restrict__ X,
    const float* __restrict__ bias, float* __restrict__ S)
{
    __shared__ float As[BK][BM + 4];
    __shared__ float Bs[BK][BN + 4];

    const int tid = threadIdx.x;
    const int bx = blockIdx.x;   // j tile
    const int by = blockIdx.y;   // i tile
    const int b  = blockIdx.z;   // batch

    const float* Yb = Y + (size_t)b * NSEQ * DDIM;
    const float* Xb = X + (size_t)b * NSEQ * DDIM;
    float*       Sb = S + (size_t)b * NSEQ * NSEQ;

    const int arow = tid >> 2;          // 0..63
    const int acol = (tid & 3) * 4;     // 0,4,8,12
    const int ty = tid >> 4;
    const int tx = tid & 15;

    float acc[TM][TN] = {};

    for (int k0 = 0; k0 < DDIM; k0 += BK) {
        // A tile: Y rows (i), transposed store
        float4 av = *(const float4*)(Yb + (size_t)(by * BM + arow) * DDIM + k0 + acol);
        As[acol + 0][arow] = av.x;
        As[acol + 1][arow] = av.y;
        As[acol + 2][arow] = av.z;
        As[acol + 3][arow] = av.w;
        // B tile: X rows (j), also transposed store (NT gemm)
        float4 bv = *(const float4*)(Xb + (size_t)(bx * BN + arow) * DDIM + k0 + acol);
        Bs[acol + 0][arow] = bv.x;
        Bs[acol + 1][arow] = bv.y;
        Bs[acol + 2][arow] = bv.z;
        Bs[acol + 3][arow] = bv.w;
        __syncthreads();

#pragma unroll
        for (int k = 0; k < BK; k++) {
            float a[TM], bb[TN];
#pragma unroll
            for (int i = 0; i < TM; i++) a[i] = As[k][ty * TM + i];
#pragma unroll
            for (int j = 0; j < TN; j++) bb[j] = Bs[k][tx * TN + j];
#pragma unroll
            for (int i = 0; i < TM; i++)
#pragma unroll
                for (int j = 0; j < TN; j++)
                    acc[i][j] += a[i] * bb[j];
        }
        __syncthreads();
    }

    const float bv = bias[0];
#pragma unroll
    for (int i = 0; i < TM; i++) {
        const int gi = by * BM + ty * TM + i;
        float4 v;
        float* vp = &v.x;
#pragma unroll
        for (int j = 0; j < TN; j++) {
            const int gj = bx * BN + tx * TN + j;
            float val = acc[i][j] + bv;
            if (gi == gj) val = 0.0f;
            vp[j] = val;
        }
        *(float4*)(Sb + (size_t)gi * NSEQ + bx * BN + tx * TN) = v;
    }
}

extern "C" void kernel_launch(void* const* d_in, const int* in_sizes, int n_in,
                              void* d_out, int out_size)
{
    const float* X = (const float*)d_in[0];   // (32, 512, 512)
    const float* W = (const float*)d_in[1];   // (512, 512)
    const float* b = (const float*)d_in[2];   // scalar
    float* S = (float*)d_out;                 // (32, 512, 512)

    float* Y;
    cudaGetSymbolAddress((void**)&Y, g_Y);

    // GEMM1: Y = X @ W, M = 32*512 = 16384
    {
        dim3 grid(DDIM / BN, (BATCH * NSEQ) / BM);
        gemm_xw<<<grid, 256>>>(X, W, Y, BATCH * NSEQ, DDIM, DDIM);
    }
    // GEMM2: S[b] = Y[b] @ X[b]^T (+bias, zero diag)
    {
        dim3 grid(NSEQ / BN, NSEQ / BM, BATCH);
        gemm_yxt<<<grid, 256>>>(Y, X, b, S);
    }
}

// round 6
// speedup vs baseline: 1.7898x; 1.7898x over previous
#include <cuda_runtime.h>
#include <cuda_fp16.h>
#include <cstdint>

#define BATCH 32
#define NSEQ  512
#define DDIM  512
#define KHALF 1024              // halves per split row: [0:512)=hi, [512:1024)=lo

#define BM 128
#define BN 128
#define BK 32
#define NCHUNK (DDIM / BK)      // 16
#define STAGES 3
#define A_BYTES (BM * 128)      // 128 rows x 128B (32 hi + 32 lo halves)
#define STAGE_BYTES (2 * A_BYTES)           // A + B = 32768
#define SMEM_TOTAL (STAGES * STAGE_BYTES)   // 98304

// Scratch (device globals — no allocation allowed)
__device__ __half g_Xs[BATCH * NSEQ * KHALF];   // split X
__device__ __half g_Ws[DDIM * KHALF];           // split W^T
__device__ __half g_Ys[BATCH * NSEQ * KHALF];   // split Y = X@W

// ---------------------------------------------------------------------------
__device__ __forceinline__ uint32_t smem_u32(const void* p) {
    uint32_t a;
    asm("{ .reg .u64 t; cvta.to.shared.u64 t, %1; cvt.u32.u64 %0, t; }"
        : "=r"(a) : "l"(p));
    return a;
}

__device__ __forceinline__ void cp16(uint32_t s, const void* g) {
    asm volatile("cp.async.cg.shared.global [%0], [%1], 16;" :: "r"(s), "l"(g));
}
#define CP_COMMIT() asm volatile("cp.async.commit_group;" ::: "memory")
#define CP_WAIT1()  asm volatile("cp.async.wait_group 1;" ::: "memory")

#define LDSM4(r, addr)                                                         \
    asm volatile("ldmatrix.sync.aligned.m8n8.x4.shared.b16 {%0,%1,%2,%3}, [%4];" \
        : "=r"((r)[0]), "=r"((r)[1]), "=r"((r)[2]), "=r"((r)[3]) : "r"(addr))

#define MMA16816(d, a, b0, b1)                                                 \
    asm volatile("mma.sync.aligned.m16n8k16.row.col.f32.f16.f16.f32 "          \
        "{%0,%1,%2,%3}, {%4,%5,%6,%7}, {%8,%9}, {%0,%1,%2,%3};"                \
        : "+f"((d)[0]), "+f"((d)[1]), "+f"((d)[2]), "+f"((d)[3])               \
        : "r"((a)[0]), "r"((a)[1]), "r"((a)[2]), "r"((a)[3]), "r"(b0), "r"(b1))

__device__ __forceinline__ void split2(float x, __half& h, __half& l) {
    h = __float2half_rn(x);
    l = __float2half_rn(x - __half2float(h));
}

// ---------------------------------------------------------------------------
// Split X: fp32 [rows][512] -> halves [rows][1024] (hi | lo)
// ---------------------------------------------------------------------------
__global__ void split_fp32(const float* __restrict__ in, __half* __restrict__ out) {
    int idx = blockIdx.x * blockDim.x + threadIdx.x;   // one per 4 elems
    int row = idx >> 7;                                 // 128 quads per row
    int k = (idx & 127) * 4;
    float4 v = *(const float4*)(in + (size_t)row * DDIM + k);
    __half h0, l0, h1, l1, h2, l2, h3, l3;
    split2(v.x, h0, l0); split2(v.y, h1, l1);
    split2(v.z, h2, l2); split2(v.w, h3, l3);
    __half* o = out + (size_t)row * KHALF;
    *(__half2*)(o + k)           = __halves2half2(h0, h1);
    *(__half2*)(o + k + 2)       = __halves2half2(h2, h3);
    *(__half2*)(o + 512 + k)     = __halves2half2(l0, l1);
    *(__half2*)(o + 512 + k + 2) = __halves2half2(l2, l3);
}

// ---------------------------------------------------------------------------
// Transpose + split W: out[n][k]=split(W[k][n])
// ---------------------------------------------------------------------------
__global__ void transpose_split(const float* __restrict__ W, __half* __restrict__ out) {
    __shared__ float t[32][33];
    int bx = blockIdx.x, by = blockIdx.y;
    int tx = threadIdx.x, ty = threadIdx.y;
    int x = bx * 32 + tx;
#pragma unroll
    for (int i = 0; i < 32; i += 8)
        t[ty + i][tx] = W[(size_t)(by * 32 + ty + i) * DDIM + x];
    __syncthreads();
    int k = by * 32 + tx;
#pragma unroll
    for (int i = 0; i < 32; i += 8) {
        int n = bx * 32 + ty + i;
        __half h, l;
        split2(t[tx][ty + i], h, l);
        out[(size_t)n * KHALF + k] = h;
        out[(size_t)n * KHALF + 512 + k] = l;
    }
}

// ---------------------------------------------------------------------------
// NT GEMM, f16 2-term split, 3 mma passes: C = A*B^T (+bias, zero-diag)
// A,B: split-half rows [*, 1024]. mode 0: write split halves to Cy.
// mode 1: write fp32 to Cs with bias + zero diagonal.
// ---------------------------------------------------------------------------
__global__ __launch_bounds__(256, 1) void gemm_f16s(
    const __half* __restrict__ A, const __half* __restrict__ B,
    __half* __restrict__ Cy, float* __restrict__ Cs,
    const float* __restrict__ bias,
    int aBatchRows, int bBatchRows, int mode)
{
    extern __shared__ __align__(128) char smem[];
    const uint32_t sb = smem_u32(smem);
    const int tid = threadIdx.x;
    const int lane = tid & 31;
    const int wid = tid >> 5;
    const int warp_m = wid & 1;          // 2 -> 64 rows each
    const int warp_n = wid >> 1;         // 4 -> 32 cols each

    const int tn = blockIdx.x, tm = blockIdx.y, bz = blockIdx.z;

    const __half* Arow = A + ((size_t)bz * aBatchRows + (size_t)tm * BM) * KHALF;
    const __half* Brow = B + ((size_t)bz * bBatchRows + (size_t)tn * BN) * KHALF;

    float acc[4][4][4] = {};             // [mt][nt][4]

    // ---- chunk loader: rows split across 2 threads (hi/lo halves) ----
    const int lr = tid >> 1;             // 0..127
    const int lsel = tid & 1;            // 0=hi, 1=lo
    auto load_chunk = [&](int c) {
        const uint32_t base = sb + (c % STAGES) * STAGE_BYTES;
        const __half* ga = Arow + (size_t)lr * KHALF + lsel * 512 + c * BK;
        const __half* gb = Brow + (size_t)lr * KHALF + lsel * 512 + c * BK;
#pragma unroll
        for (int j = 0; j < 4; j++) {
            const int cc = lsel * 4 + j;
            const uint32_t so = lr * 128 + ((cc ^ (lr & 7)) << 4);
            cp16(base + so, ga + j * 8);
            cp16(base + A_BYTES + so, gb + j * 8);
        }
    };

    load_chunk(0); CP_COMMIT();
    load_chunk(1); CP_COMMIT();

    const int flr = lane & 15, flc = lane >> 4;

#pragma unroll 1
    for (int kc = 0; kc < NCHUNK; kc++) {
        CP_WAIT1();
        __syncthreads();

        if (kc + 2 < NCHUNK) load_chunk(kc + 2);
        CP_COMMIT();

        const uint32_t abase = sb + (kc % STAGES) * STAGE_BYTES;
        const uint32_t bbase = abase + A_BYTES;

#pragma unroll
        for (int s = 0; s < 2; s++) {    // two k16 per chunk
            uint32_t ah[4][4], al[4][4], bh[2][4], bl[2][4];
#pragma unroll
            for (int mt = 0; mt < 4; mt++) {
                const int r = warp_m * 64 + mt * 16 + flr;
                const int cH = s * 2 + flc;
                const int cL = 4 + s * 2 + flc;
                LDSM4(ah[mt], abase + r * 128 + ((cH ^ (r & 7)) << 4));
                LDSM4(al[mt], abase + r * 128 + ((cL ^ (r & 7)) << 4));
            }
#pragma unroll
            for (int g = 0; g < 2; g++) {
                const int r = warp_n * 32 + g * 16 + flr;
                const int cH = s * 2 + flc;
                const int cL = 4 + s * 2 + flc;
                LDSM4(bh[g], bbase + r * 128 + ((cH ^ (r & 7)) << 4));
                LDSM4(bl[g], bbase + r * 128 + ((cL ^ (r & 7)) << 4));
            }
#pragma unroll
            for (int mt = 0; mt < 4; mt++)
#pragma unroll
                for (int nt = 0; nt < 4; nt++) {
                    const int g = nt >> 1, sub = nt & 1;
                    MMA16816(acc[mt][nt], ah[mt], bh[g][sub], bh[g][sub + 2]);
                    MMA16816(acc[mt][nt], ah[mt], bl[g][sub], bl[g][sub + 2]);
                    MMA16816(acc[mt][nt], al[mt], bh[g][sub], bh[g][sub + 2]);
                }
        }
        __syncthreads();
    }

    // ---- epilogue ----
    const int mBaseG = bz * aBatchRows + tm * BM;     // global A/Y row base
    const int mBaseL = tm * BM;                        // row within batch
    const float bv = (mode == 1) ? bias[0] : 0.0f;

#pragma unroll
    for (int mt = 0; mt < 4; mt++) {
#pragma unroll
        for (int nt = 0; nt < 4; nt++) {
            const int r0 = warp_m * 64 + mt * 16 + (lane >> 2);
            const int col = tn * BN + warp_n * 32 + nt * 8 + (lane & 3) * 2;
            const float* d = acc[mt][nt];
            if (mode == 0) {
                __half* o0 = Cy + (size_t)(mBaseG + r0) * KHALF + col;
                __half* o1 = Cy + (size_t)(mBaseG + r0 + 8) * KHALF + col;
                __half h0, l0, h1, l1;
                split2(d[0], h0, l0); split2(d[1], h1, l1);
                *(__half2*)(o0)       = __halves2half2(h0, h1);
                *(__half2*)(o0 + 512) = __halves2half2(l0, l1);
                split2(d[2], h0, l0); split2(d[3], h1, l1);
                *(__half2*)(o1)       = __halves2half2(h0, h1);
                *(__half2*)(o1 + 512) = __halves2half2(l0, l1);
            } else {
                float* s0 = Cs + (size_t)bz * NSEQ * NSEQ + (size_t)(mBaseL + r0) * NSEQ + col;
                float* s1 = s0 + 8 * NSEQ;
                const int i0 = mBaseL + r0, i1 = i0 + 8;
                float2 v0 = make_float2(d[0] + bv, d[1] + bv);
                float2 v1 = make_float2(d[2] + bv, d[3] + bv);
                if (i0 == col) v0.x = 0.0f;
                if (i0 == col + 1) v0.y = 0.0f;
                if (i1 == col) v1.x = 0.0f;
                if (i1 == col + 1) v1.y = 0.0f;
                *(float2*)s0 = v0;
                *(float2*)s1 = v1;
            }
        }
    }
}

// ---------------------------------------------------------------------------
extern "C" void kernel_launch(void* const* d_in, const int* in_sizes, int n_in,
                              void* d_out, int out_size)
{
    const float* X = (const float*)d_in[0];   // (32, 512, 512)
    const float* W = (const float*)d_in[1];   // (512, 512)
    const float* b = (const float*)d_in[2];   // scalar
    float* S = (float*)d_out;                 // (32, 512, 512)

    __half *Xs, *Ws, *Ys;
    cudaGetSymbolAddress((void**)&Xs, g_Xs);
    cudaGetSymbolAddress((void**)&Ws, g_Ws);
    cudaGetSymbolAddress((void**)&Ys, g_Ys);

    cudaFuncSetAttribute(gemm_f16s, cudaFuncAttributeMaxDynamicSharedMemorySize,
                         SMEM_TOTAL);

    // Prep: split X, transpose+split W
    split_fp32<<<(BATCH * NSEQ * DDIM / 4) / 256, 256>>>(X, Xs);
    transpose_split<<<dim3(16, 16), dim3(32, 8)>>>(W, Ws);

    // GEMM1: Y = X @ W  (A rows global 0..16383, B = Ws shared)
    gemm_f16s<<<dim3(DDIM / BN, (BATCH * NSEQ) / BM, 1), 256, SMEM_TOTAL>>>(
        Xs, Ws, Ys, nullptr, b, 0, 0, 0);

    // GEMM2: S[b] = Y[b] @ X[b]^T + bias, diag zeroed
    gemm_f16s<<<dim3(NSEQ / BN, NSEQ / BM, BATCH), 256, SMEM_TOTAL>>>(
        Ys, Xs, nullptr, S, b, NSEQ, NSEQ, 1);
}